// round 16
// baseline (speedup 1.0000x reference)
#include <cuda_runtime.h>

#define D     2048
#define SEQ   4096
#define BB    4
#define ROWS  16384      // BB*SEQ
#define RS    6          // ar_ssm rank
#define RF    21         // ffn rank
#define EPS   1e-6f

typedef unsigned long long ull;

// scratch (device globals — no allocations allowed)
__device__ float g_u[RS * ROWS];                     // u transposed: [r][row]
__device__ __align__(16) ull g_hsp[RS * ROWS / 2];   // scan states, packed row-pairs
__device__ __align__(16) ull g_gp [RF * ROWS / 2];   // gelu(t), packed row-pairs [j][row/2]

// -------- f32x2 helpers --------
__device__ __forceinline__ ull pk(float a, float b) {
    ull r; asm("mov.b64 %0,{%1,%2};" : "=l"(r) : "f"(a), "f"(b)); return r;
}
__device__ __forceinline__ ull pk1(float a) { return pk(a, a); }
__device__ __forceinline__ ull f2fma(ull a, ull b, ull c) {
    ull d; asm("fma.rn.f32x2 %0,%1,%2,%3;" : "=l"(d) : "l"(a), "l"(b), "l"(c));
    return d;
}
__device__ __forceinline__ void upk(ull v, float& a, float& b) {
    asm("mov.b64 {%0,%1},%2;" : "=f"(a), "=f"(b) : "l"(v));
}
__device__ __forceinline__ float wred(float v) {
#pragma unroll
    for (int off = 16; off > 0; off >>= 1)
        v += __shfl_xor_sync(0xffffffffu, v, off);
    return v;
}

// ============================================================================
// K1: per-row ssq(x) and u = rmsnorm(x,w1) @ U   (U*w1 folded into smem).
// 4 rows per warp; row pairs packed into f32x2; prefetched x loads.
// ============================================================================
__global__ void __launch_bounds__(256) k1_kernel(const float* __restrict__ x,
                                                 const float* __restrict__ w1,
                                                 const float* __restrict__ U) {
    extern __shared__ float Us[];                 // [RS][D]
    int tid = threadIdx.x;
    for (int d = tid; d < D; d += 256) {
        float w = w1[d];
#pragma unroll
        for (int r = 0; r < RS; r++) Us[r * D + d] = U[d * RS + r] * w;
    }
    __syncthreads();

    int lane = tid & 31;
    int gw = (blockIdx.x * 256 + tid) >> 5;
    int nw = (gridDim.x * 256) >> 5;

    for (int tile = gw; tile < ROWS / 4; tile += nw) {
        int row0 = tile * 4;
        const float* xp = x + (size_t)row0 * D;

        ull ss0 = 0ull, ss1 = 0ull;
        ull u20[RS], u21[RS];
#pragma unroll
        for (int r = 0; r < RS; r++) { u20[r] = 0ull; u21[r] = 0ull; }

        float4 xa = *(const float4*)(xp + lane * 4);
        float4 xb = *(const float4*)(xp + D + lane * 4);
        float4 xc = *(const float4*)(xp + 2 * D + lane * 4);
        float4 xd = *(const float4*)(xp + 3 * D + lane * 4);

#pragma unroll 1
        for (int it = 0; it < 16; it++) {
            int d0 = it * 128 + lane * 4;
            float4 na, nb, nc, nd;
            if (it != 15) {
                int dn = d0 + 128;
                na = *(const float4*)(xp + dn);
                nb = *(const float4*)(xp + D + dn);
                nc = *(const float4*)(xp + 2 * D + dn);
                nd = *(const float4*)(xp + 3 * D + dn);
            }
            float A[4], Bv[4], C[4], Dv[4];
            *(float4*)A = xa; *(float4*)Bv = xb; *(float4*)C = xc; *(float4*)Dv = xd;

            float uw[RS][4];
#pragma unroll
            for (int r = 0; r < RS; r++)
                *(float4*)uw[r] = *(const float4*)(Us + r * D + d0);
#pragma unroll
            for (int d = 0; d < 4; d++) {
                ull p0 = pk(A[d], Bv[d]);
                ull p1 = pk(C[d], Dv[d]);
                ss0 = f2fma(p0, p0, ss0);
                ss1 = f2fma(p1, p1, ss1);
#pragma unroll
                for (int r = 0; r < RS; r++) {
                    ull w2 = pk1(uw[r][d]);
                    u20[r] = f2fma(p0, w2, u20[r]);
                    u21[r] = f2fma(p1, w2, u21[r]);
                }
            }
            xa = na; xb = nb; xc = nc; xd = nd;
        }
        float ss[4], myu[4];
        { float a, b; upk(ss0, a, b); ss[0] = a; ss[1] = b;
                      upk(ss1, a, b); ss[2] = a; ss[3] = b; }
#pragma unroll
        for (int rr = 0; rr < 4; rr++) ss[rr] = wred(ss[rr]);
#pragma unroll
        for (int r = 0; r < RS; r++) {
            float a, b;
            upk(u20[r], a, b);
            a = wred(a); b = wred(b);
            if (lane == r) { myu[0] = a; myu[1] = b; }
            upk(u21[r], a, b);
            a = wred(a); b = wred(b);
            if (lane == r) { myu[2] = a; myu[3] = b; }
        }
#pragma unroll
        for (int rr = 0; rr < 4; rr++) {
            float inv = rsqrtf(ss[rr] * (1.0f / D) + EPS);
            if (lane < RS) g_u[lane * ROWS + row0 + rr] = inv * myu[rr];
        }
    }
}

// ============================================================================
// K2: linear recurrence h_s = a*h_{s-1} + u_s along S, per (b,r).
// Output written PRE-PACKED as f32x2 row-pairs into g_hsp.
// ============================================================================
__global__ void __launch_bounds__(128) k2_scan(const float* __restrict__ lam) {
    int b = blockIdx.x / RS, r = blockIdx.x % RS;
    float a = 1.0f / (1.0f + expf(-lam[r]));
    const float* up = g_u + r * ROWS + b * SEQ;
    ull* hp = g_hsp + (r * ROWS + b * SEQ) / 2;
    int t = threadIdx.x;
    const int L = 32;

    float loc[L];
#pragma unroll
    for (int kk = 0; kk < L / 4; kk++)
        *(float4*)(loc + kk * 4) = *(const float4*)(up + t * L + kk * 4);

    float h = 0.0f;
#pragma unroll
    for (int k = 0; k < L; k++) { h = a * h + loc[k]; loc[k] = h; }

    float aL = a;
#pragma unroll
    for (int i = 0; i < 5; i++) aL = aL * aL;     // a^32

    __shared__ float sf[128];
    float T = h;
    sf[t] = T;
    __syncthreads();
    float m = aL;
    for (int off = 1; off < 128; off <<= 1) {
        float prev = (t >= off) ? sf[t - off] : 0.0f;
        __syncthreads();
        T += m * prev;
        sf[t] = T;
        m = m * m;
        __syncthreads();
    }
    float Hin = (t > 0) ? sf[t - 1] : 0.0f;
    float p = a;
#pragma unroll
    for (int k = 0; k < L; k++) { loc[k] = loc[k] + p * Hin; p *= a; }

    ull* hp2 = hp + t * (L / 2);
#pragma unroll
    for (int kk = 0; kk < L / 4; kk++) {
        ulonglong2 v;
        v.x = pk(loc[4 * kk],     loc[4 * kk + 1]);
        v.y = pk(loc[4 * kk + 2], loc[4 * kk + 3]);
        *(ulonglong2*)(hp2 + 2 * kk) = v;
    }
}

// ============================================================================
// K3a: x1 = x + h@V (recomputed); ssq(x1); t = (w2*x1/rms)@W1; g = gelu(t).
// g written PRE-PACKED into g_gp[j][row/2]. V + W1^T*w2 in smem (216KB).
// ============================================================================
#define T3A 320
__global__ void __launch_bounds__(T3A) k3a_kernel(const float* __restrict__ x,
                                                  const float* __restrict__ V,
                                                  const float* __restrict__ w2,
                                                  const float* __restrict__ W1) {
    extern __shared__ float sm[];
    float* Vs  = sm;              // [RS][D]
    float* W1s = sm + RS * D;     // [RF][D] transposed, * norm2_w
    int tid = threadIdx.x;
    for (int i = tid; i < RS * D; i += T3A) Vs[i] = V[i];
    for (int d = tid; d < D; d += T3A) {
        float w = w2[d];
#pragma unroll
        for (int j = 0; j < RF; j++) W1s[j * D + d] = W1[d * RF + j] * w;
    }
    __syncthreads();

    int lane = tid & 31;
    int gw = (blockIdx.x * T3A + tid) >> 5;
    int nw = (gridDim.x * T3A) >> 5;

    for (int tile = gw; tile < ROWS / 4; tile += nw) {
        int row0 = tile * 4;
        const float* xp = x + (size_t)row0 * D;

        ull h0[RS], h1[RS];
#pragma unroll
        for (int r = 0; r < RS; r++) {
            ulonglong2 hv = *(const ulonglong2*)(g_hsp + r * (ROWS / 2) + (row0 >> 1));
            h0[r] = hv.x;
            h1[r] = hv.y;
        }
        ull ss0 = 0ull, ss1 = 0ull;
        ull t0[RF], t1[RF];
#pragma unroll
        for (int j = 0; j < RF; j++) { t0[j] = 0ull; t1[j] = 0ull; }

        float4 xa = *(const float4*)(xp + lane * 4);
        float4 xb = *(const float4*)(xp + D + lane * 4);
        float4 xc = *(const float4*)(xp + 2 * D + lane * 4);
        float4 xd = *(const float4*)(xp + 3 * D + lane * 4);

#pragma unroll 1
        for (int it = 0; it < 16; it++) {
            int d0 = it * 128 + lane * 4;
            float4 na, nb, nc, nd;
            if (it != 15) {
                int dn = d0 + 128;
                na = *(const float4*)(xp + dn);
                nb = *(const float4*)(xp + D + dn);
                nc = *(const float4*)(xp + 2 * D + dn);
                nd = *(const float4*)(xp + 3 * D + dn);
            }
            float A[4], Bv[4], C[4], Dv[4];
            *(float4*)A = xa; *(float4*)Bv = xb; *(float4*)C = xc; *(float4*)Dv = xd;

            float vv[RS][4];
#pragma unroll
            for (int r = 0; r < RS; r++)
                *(float4*)vv[r] = *(const float4*)(Vs + r * D + d0);

            ull x10[4], x11[4];
#pragma unroll
            for (int d = 0; d < 4; d++) {
                ull p0 = pk(A[d], Bv[d]);
                ull p1 = pk(C[d], Dv[d]);
#pragma unroll
                for (int r = 0; r < RS; r++) {
                    ull v2 = pk1(vv[r][d]);
                    p0 = f2fma(h0[r], v2, p0);
                    p1 = f2fma(h1[r], v2, p1);
                }
                x10[d] = p0; x11[d] = p1;
                ss0 = f2fma(p0, p0, ss0);
                ss1 = f2fma(p1, p1, ss1);
            }
#pragma unroll
            for (int j = 0; j < RF; j++) {
                float wv[4];
                *(float4*)wv = *(const float4*)(W1s + j * D + d0);
#pragma unroll
                for (int d = 0; d < 4; d++) {
                    ull w2p = pk1(wv[d]);
                    t0[j] = f2fma(x10[d], w2p, t0[j]);
                    t1[j] = f2fma(x11[d], w2p, t1[j]);
                }
            }
            xa = na; xb = nb; xc = nc; xd = nd;
        }
        float ss[4], myt[4];
        { float a, b; upk(ss0, a, b); ss[0] = a; ss[1] = b;
                      upk(ss1, a, b); ss[2] = a; ss[3] = b; }
#pragma unroll
        for (int rr = 0; rr < 4; rr++) ss[rr] = wred(ss[rr]);
#pragma unroll
        for (int j = 0; j < RF; j++) {
            float a, b;
            upk(t0[j], a, b);
            a = wred(a); b = wred(b);
            if (lane == j) { myt[0] = a; myt[1] = b; }
            upk(t1[j], a, b);
            a = wred(a); b = wred(b);
            if (lane == j) { myt[2] = a; myt[3] = b; }
        }
        if (lane < RF) {
            float gv[4];
#pragma unroll
            for (int rr = 0; rr < 4; rr++) {
                float inv = rsqrtf(ss[rr] * (1.0f / D) + EPS);
                float tv = inv * myt[rr];
                gv[rr] = 0.5f * tv *
                    (1.0f + tanhf(0.7978845608028654f * (tv + 0.044715f * tv * tv * tv)));
            }
            ulonglong2 gvp;
            gvp.x = pk(gv[0], gv[1]);
            gvp.y = pk(gv[2], gv[3]);
            *(ulonglong2*)(g_gp + lane * (ROWS / 2) + (row0 >> 1)) = gvp;
        }
    }
}

// ============================================================================
// K3b: out = (x + h@V) + g @ W2.    FLATTENED work units.
// 32768 units of (8 rows x 128 cols); each warp takes one 4-col slice of
// 8 rows per unit: no d-loop, no reductions, ~15.8 units/warp (1.01 balance).
// h/g read as pre-packed f32x2 broadcasts (L1/L2-cached); V/W2 in smem.
// ============================================================================
#define T3B   448
#define NUNIT ((ROWS / 8) * 16)    // 32768
__global__ void __launch_bounds__(T3B) k3b_kernel(const float* __restrict__ x,
                                                  const float* __restrict__ V,
                                                  const float* __restrict__ W2,
                                                  float* __restrict__ out) {
    extern __shared__ float sm[];
    float* Vs  = sm;              // [RS][D]
    float* W2s = sm + RS * D;     // [RF][D]
    int tid = threadIdx.x;
    for (int i = tid; i < RS * D; i += T3B) Vs[i] = V[i];
    for (int i = tid; i < RF * D; i += T3B) W2s[i] = W2[i];
    __syncthreads();

    int lane = tid & 31;
    int gwid = (blockIdx.x * T3B + tid) >> 5;
    int nw = (gridDim.x * T3B) >> 5;

    int u = gwid;
    float xc[8][4];
    if (u < NUNIT) {
        int row0 = (u >> 4) * 8;
        int d0 = (u & 15) * 128 + lane * 4;
        const float* xp = x + (size_t)row0 * D + d0;
#pragma unroll
        for (int i = 0; i < 8; i++)
            *(float4*)xc[i] = *(const float4*)(xp + (size_t)i * D);
    }

#pragma unroll 1
    for (; u < NUNIT; u += nw) {
        // prefetch next unit's x while computing this one
        int un = u + nw;
        float xn[8][4];
        if (un < NUNIT) {
            int row0n = (un >> 4) * 8;
            int d0n = (un & 15) * 128 + lane * 4;
            const float* xpn = x + (size_t)row0n * D + d0n;
#pragma unroll
            for (int i = 0; i < 8; i++)
                *(float4*)xn[i] = *(const float4*)(xpn + (size_t)i * D);
        }

        int row0 = (u >> 4) * 8;
        int d0 = (u & 15) * 128 + lane * 4;
        int rp = row0 >> 1;

        ull o[4][4];
#pragma unroll
        for (int p = 0; p < 4; p++)
#pragma unroll
            for (int d = 0; d < 4; d++)
                o[p][d] = pk(xc[2 * p][d], xc[2 * p + 1][d]);

#pragma unroll
        for (int r = 0; r < RS; r++) {
            ulonglong2 hA = *(const ulonglong2*)(g_hsp + r * (ROWS / 2) + rp);
            ulonglong2 hB = *(const ulonglong2*)(g_hsp + r * (ROWS / 2) + rp + 2);
            float vv[4];
            *(float4*)vv = *(const float4*)(Vs + r * D + d0);
#pragma unroll
            for (int d = 0; d < 4; d++) {
                ull w = pk1(vv[d]);
                o[0][d] = f2fma(hA.x, w, o[0][d]);
                o[1][d] = f2fma(hA.y, w, o[1][d]);
                o[2][d] = f2fma(hB.x, w, o[2][d]);
                o[3][d] = f2fma(hB.y, w, o[3][d]);
            }
        }

#pragma unroll 7
        for (int j = 0; j < RF; j++) {
            ulonglong2 gA = *(const ulonglong2*)(g_gp + j * (ROWS / 2) + rp);
            ulonglong2 gB = *(const ulonglong2*)(g_gp + j * (ROWS / 2) + rp + 2);
            float wv[4];
            *(float4*)wv = *(const float4*)(W2s + j * D + d0);
#pragma unroll
            for (int d = 0; d < 4; d++) {
                ull w = pk1(wv[d]);
                o[0][d] = f2fma(gA.x, w, o[0][d]);
                o[1][d] = f2fma(gA.y, w, o[1][d]);
                o[2][d] = f2fma(gB.x, w, o[2][d]);
                o[3][d] = f2fma(gB.y, w, o[3][d]);
            }
        }

        float* op = out + (size_t)row0 * D + d0;
#pragma unroll
        for (int p = 0; p < 4; p++) {
            float ra[4], rb[4];
#pragma unroll
            for (int d = 0; d < 4; d++) upk(o[p][d], ra[d], rb[d]);
            __stcs((float4*)(op + (size_t)(2 * p) * D),     *(float4*)ra);
            __stcs((float4*)(op + (size_t)(2 * p + 1) * D), *(float4*)rb);
        }
#pragma unroll
        for (int i = 0; i < 8; i++)
#pragma unroll
            for (int d = 0; d < 4; d++) xc[i][d] = xn[i][d];
    }
}

// ============================================================================
extern "C" void kernel_launch(void* const* d_in, const int* in_sizes, int n_in,
                              void* d_out, int out_size) {
    const float* x   = (const float*)d_in[0];
    const float* n1w = (const float*)d_in[1];
    const float* U   = (const float*)d_in[2];
    const float* lam = (const float*)d_in[3];
    const float* V   = (const float*)d_in[4];
    const float* n2w = (const float*)d_in[5];
    const float* W1  = (const float*)d_in[6];
    const float* W2  = (const float*)d_in[7];
    float* out = (float*)d_out;

    const int smem1 = RS * D * (int)sizeof(float);           // 48 KB
    const int smem3 = (RS + RF) * D * (int)sizeof(float);    // 216 KB

    cudaFuncSetAttribute(k1_kernel,
                         cudaFuncAttributeMaxDynamicSharedMemorySize, smem1);
    cudaFuncSetAttribute(k3a_kernel,
                         cudaFuncAttributeMaxDynamicSharedMemorySize, smem3);
    cudaFuncSetAttribute(k3b_kernel,
                         cudaFuncAttributeMaxDynamicSharedMemorySize, smem3);

    k1_kernel<<<592, 256, smem1>>>(x, n1w, U);          // 4 CTAs/SM
    k2_scan<<<BB * RS, 128>>>(lam);
    k3a_kernel<<<148, T3A, smem3>>>(x, V, n2w, W1);
    k3b_kernel<<<148, T3B, smem3>>>(x, V, W2, out);
}

// round 17
// speedup vs baseline: 1.1942x; 1.1942x over previous
#include <cuda_runtime.h>

#define D     2048
#define SEQ   4096
#define BB    4
#define ROWS  16384      // BB*SEQ
#define RS    6          // ar_ssm rank
#define RF    21         // ffn rank
#define EPS   1e-6f

typedef unsigned long long ull;

// scratch (device globals — no allocations allowed)
__device__ float g_u[RS * ROWS];                     // u transposed: [r][row]
__device__ __align__(16) ull g_hsp[RS * ROWS / 2];   // scan states, packed row-pairs

// -------- f32x2 helpers --------
__device__ __forceinline__ ull pk(float a, float b) {
    ull r; asm("mov.b64 %0,{%1,%2};" : "=l"(r) : "f"(a), "f"(b)); return r;
}
__device__ __forceinline__ ull pk1(float a) { return pk(a, a); }
__device__ __forceinline__ ull f2fma(ull a, ull b, ull c) {
    ull d; asm("fma.rn.f32x2 %0,%1,%2,%3;" : "=l"(d) : "l"(a), "l"(b), "l"(c));
    return d;
}
__device__ __forceinline__ void upk(ull v, float& a, float& b) {
    asm("mov.b64 {%0,%1},%2;" : "=f"(a), "=f"(b) : "l"(v));
}
__device__ __forceinline__ float wred(float v) {
#pragma unroll
    for (int off = 16; off > 0; off >>= 1)
        v += __shfl_xor_sync(0xffffffffu, v, off);
    return v;
}

// ============================================================================
// K1: per-row ssq(x) and u = rmsnorm(x,w1) @ U   (U*w1 folded into smem).
// 4 rows per warp; row pairs packed into f32x2; prefetched x loads.
// ============================================================================
__global__ void __launch_bounds__(256) k1_kernel(const float* __restrict__ x,
                                                 const float* __restrict__ w1,
                                                 const float* __restrict__ U) {
    extern __shared__ float Us[];                 // [RS][D]
    int tid = threadIdx.x;
    for (int d = tid; d < D; d += 256) {
        float w = w1[d];
#pragma unroll
        for (int r = 0; r < RS; r++) Us[r * D + d] = U[d * RS + r] * w;
    }
    __syncthreads();

    int lane = tid & 31;
    int gw = (blockIdx.x * 256 + tid) >> 5;
    int nw = (gridDim.x * 256) >> 5;

    for (int tile = gw; tile < ROWS / 4; tile += nw) {
        int row0 = tile * 4;
        const float* xp = x + (size_t)row0 * D;

        ull ss0 = 0ull, ss1 = 0ull;
        ull u20[RS], u21[RS];
#pragma unroll
        for (int r = 0; r < RS; r++) { u20[r] = 0ull; u21[r] = 0ull; }

        float4 xa = *(const float4*)(xp + lane * 4);
        float4 xb = *(const float4*)(xp + D + lane * 4);
        float4 xc = *(const float4*)(xp + 2 * D + lane * 4);
        float4 xd = *(const float4*)(xp + 3 * D + lane * 4);

#pragma unroll 1
        for (int it = 0; it < 16; it++) {
            int d0 = it * 128 + lane * 4;
            float4 na, nb, nc, nd;
            if (it != 15) {
                int dn = d0 + 128;
                na = *(const float4*)(xp + dn);
                nb = *(const float4*)(xp + D + dn);
                nc = *(const float4*)(xp + 2 * D + dn);
                nd = *(const float4*)(xp + 3 * D + dn);
            }
            float A[4], Bv[4], C[4], Dv[4];
            *(float4*)A = xa; *(float4*)Bv = xb; *(float4*)C = xc; *(float4*)Dv = xd;

            float uw[RS][4];
#pragma unroll
            for (int r = 0; r < RS; r++)
                *(float4*)uw[r] = *(const float4*)(Us + r * D + d0);
#pragma unroll
            for (int d = 0; d < 4; d++) {
                ull p0 = pk(A[d], Bv[d]);
                ull p1 = pk(C[d], Dv[d]);
                ss0 = f2fma(p0, p0, ss0);
                ss1 = f2fma(p1, p1, ss1);
#pragma unroll
                for (int r = 0; r < RS; r++) {
                    ull w2 = pk1(uw[r][d]);
                    u20[r] = f2fma(p0, w2, u20[r]);
                    u21[r] = f2fma(p1, w2, u21[r]);
                }
            }
            xa = na; xb = nb; xc = nc; xd = nd;
        }
        float ss[4], myu[4];
        { float a, b; upk(ss0, a, b); ss[0] = a; ss[1] = b;
                      upk(ss1, a, b); ss[2] = a; ss[3] = b; }
#pragma unroll
        for (int rr = 0; rr < 4; rr++) ss[rr] = wred(ss[rr]);
#pragma unroll
        for (int r = 0; r < RS; r++) {
            float a, b;
            upk(u20[r], a, b);
            a = wred(a); b = wred(b);
            if (lane == r) { myu[0] = a; myu[1] = b; }
            upk(u21[r], a, b);
            a = wred(a); b = wred(b);
            if (lane == r) { myu[2] = a; myu[3] = b; }
        }
#pragma unroll
        for (int rr = 0; rr < 4; rr++) {
            float inv = rsqrtf(ss[rr] * (1.0f / D) + EPS);
            if (lane < RS) g_u[lane * ROWS + row0 + rr] = inv * myu[rr];
        }
    }
}

// ============================================================================
// K2: linear recurrence h_s = a*h_{s-1} + u_s along S, per (b,r).
// Output written PRE-PACKED as f32x2 row-pairs into g_hsp.
// ============================================================================
__global__ void __launch_bounds__(128) k2_scan(const float* __restrict__ lam) {
    int b = blockIdx.x / RS, r = blockIdx.x % RS;
    float a = 1.0f / (1.0f + expf(-lam[r]));
    const float* up = g_u + r * ROWS + b * SEQ;
    ull* hp = g_hsp + (r * ROWS + b * SEQ) / 2;
    int t = threadIdx.x;
    const int L = 32;

    float loc[L];
#pragma unroll
    for (int kk = 0; kk < L / 4; kk++)
        *(float4*)(loc + kk * 4) = *(const float4*)(up + t * L + kk * 4);

    float h = 0.0f;
#pragma unroll
    for (int k = 0; k < L; k++) { h = a * h + loc[k]; loc[k] = h; }

    float aL = a;
#pragma unroll
    for (int i = 0; i < 5; i++) aL = aL * aL;     // a^32

    __shared__ float sf[128];
    float T = h;
    sf[t] = T;
    __syncthreads();
    float m = aL;
    for (int off = 1; off < 128; off <<= 1) {
        float prev = (t >= off) ? sf[t - off] : 0.0f;
        __syncthreads();
        T += m * prev;
        sf[t] = T;
        m = m * m;
        __syncthreads();
    }
    float Hin = (t > 0) ? sf[t - 1] : 0.0f;
    float p = a;
#pragma unroll
    for (int k = 0; k < L; k++) { loc[k] = loc[k] + p * Hin; p *= a; }

    ull* hp2 = hp + t * (L / 2);
#pragma unroll
    for (int kk = 0; kk < L / 4; kk++) {
        ulonglong2 v;
        v.x = pk(loc[4 * kk],     loc[4 * kk + 1]);
        v.y = pk(loc[4 * kk + 2], loc[4 * kk + 3]);
        *(ulonglong2*)(hp2 + 2 * kk) = v;
    }
}

// ============================================================================
// K3 (FUSED): per 4-row tile, two passes, one warp owns the tile end-to-end.
//  pass 1: x1 = x + h@V (recomputed); ssq(x1); t = (w2*x1/rms)@W1;
//          g = gelu(t) -> staged in per-warp smem (336 B).
//  pass 2: re-read x (L2-hot), recompute x1, out = x1 + g@W2 (streaming store).
// smem: V(48K) + W1^T*w2(168K) + W2... W2 stays in gmem? NO — W2 replaces W1
// in the SAME smem region is impossible (other warps still in pass 1).
// Instead W1s holds W1^T*w2 AND W2s holds W2: that's 2*168K + 48K > limit.
// Resolution: keep V + W1^T*w2 in smem; read W2 via read-only gmem loads in
// pass 2 — W2 is 168 KB, fully L2-resident after first wave, and each warp's
// W2 load (float4/lane) is coalesced 512 B/instr — same cost class as k3b's
// LDS before. DRAM adds ~168 KB once. (L1 has only ~12 KB left; L2 services.)
// ============================================================================
#define T3 320
__global__ void __launch_bounds__(T3) k3_fused(const float* __restrict__ x,
                                               const float* __restrict__ V,
                                               const float* __restrict__ w2,
                                               const float* __restrict__ W1,
                                               const float* __restrict__ W2,
                                               float* __restrict__ out) {
    extern __shared__ float sm[];
    float* Vs  = sm;              // [RS][D]
    float* W1s = sm + RS * D;     // [RF][D] transposed, * norm2_w
    ull*   gW  = (ull*)(sm + (RS + RF) * D);   // [nwarps][RF][2]
    int tid = threadIdx.x;
    for (int i = tid; i < RS * D; i += T3) Vs[i] = V[i];
    for (int d = tid; d < D; d += T3) {
        float w = w2[d];
#pragma unroll
        for (int j = 0; j < RF; j++) W1s[j * D + d] = W1[d * RF + j] * w;
    }
    __syncthreads();

    int lane = tid & 31;
    int wid = tid >> 5;
    ull* gw = gW + wid * (RF * 2);

    int gwid = (blockIdx.x * T3 + tid) >> 5;
    int nw = (gridDim.x * T3) >> 5;

    for (int tile = gwid; tile < ROWS / 4; tile += nw) {
        int row0 = tile * 4;
        const float* xp = x + (size_t)row0 * D;
        float*       op = out + (size_t)row0 * D;

        ull h0[RS], h1[RS];
#pragma unroll
        for (int r = 0; r < RS; r++) {
            ulonglong2 hv = *(const ulonglong2*)(g_hsp + r * (ROWS / 2) + (row0 >> 1));
            h0[r] = hv.x;
            h1[r] = hv.y;
        }

        // ---------------- pass 1 ----------------
        ull ss0 = 0ull, ss1 = 0ull;
        ull t0[RF], t1[RF];
#pragma unroll
        for (int j = 0; j < RF; j++) { t0[j] = 0ull; t1[j] = 0ull; }

        float4 xa = *(const float4*)(xp + lane * 4);
        float4 xb = *(const float4*)(xp + D + lane * 4);
        float4 xc = *(const float4*)(xp + 2 * D + lane * 4);
        float4 xd = *(const float4*)(xp + 3 * D + lane * 4);

#pragma unroll 1
        for (int it = 0; it < 16; it++) {
            int d0 = it * 128 + lane * 4;
            float4 na, nb, nc, nd;
            if (it != 15) {
                int dn = d0 + 128;
                na = *(const float4*)(xp + dn);
                nb = *(const float4*)(xp + D + dn);
                nc = *(const float4*)(xp + 2 * D + dn);
                nd = *(const float4*)(xp + 3 * D + dn);
            }
            float A[4], Bv[4], C[4], Dv[4];
            *(float4*)A = xa; *(float4*)Bv = xb; *(float4*)C = xc; *(float4*)Dv = xd;

            float vv[RS][4];
#pragma unroll
            for (int r = 0; r < RS; r++)
                *(float4*)vv[r] = *(const float4*)(Vs + r * D + d0);

            ull x10[4], x11[4];
#pragma unroll
            for (int d = 0; d < 4; d++) {
                ull p0 = pk(A[d], Bv[d]);
                ull p1 = pk(C[d], Dv[d]);
#pragma unroll
                for (int r = 0; r < RS; r++) {
                    ull v2 = pk1(vv[r][d]);
                    p0 = f2fma(h0[r], v2, p0);
                    p1 = f2fma(h1[r], v2, p1);
                }
                x10[d] = p0; x11[d] = p1;
                ss0 = f2fma(p0, p0, ss0);
                ss1 = f2fma(p1, p1, ss1);
            }
#pragma unroll
            for (int j = 0; j < RF; j++) {
                float wv[4];
                *(float4*)wv = *(const float4*)(W1s + j * D + d0);
#pragma unroll
                for (int d = 0; d < 4; d++) {
                    ull w2p = pk1(wv[d]);
                    t0[j] = f2fma(x10[d], w2p, t0[j]);
                    t1[j] = f2fma(x11[d], w2p, t1[j]);
                }
            }
            xa = na; xb = nb; xc = nc; xd = nd;
        }

        // prefetch pass-2 it=0 x NOW, before the reduction tree hides L2 lat
        xa = *(const float4*)(xp + lane * 4);
        xb = *(const float4*)(xp + D + lane * 4);
        xc = *(const float4*)(xp + 2 * D + lane * 4);
        xd = *(const float4*)(xp + 3 * D + lane * 4);

        float ss[4], myt[4];
        { float a, b; upk(ss0, a, b); ss[0] = a; ss[1] = b;
                      upk(ss1, a, b); ss[2] = a; ss[3] = b; }
#pragma unroll
        for (int rr = 0; rr < 4; rr++) ss[rr] = wred(ss[rr]);
#pragma unroll
        for (int j = 0; j < RF; j++) {
            float a, b;
            upk(t0[j], a, b);
            a = wred(a); b = wred(b);
            if (lane == j) { myt[0] = a; myt[1] = b; }
            upk(t1[j], a, b);
            a = wred(a); b = wred(b);
            if (lane == j) { myt[2] = a; myt[3] = b; }
        }
        if (lane < RF) {
            float gv[4];
#pragma unroll
            for (int rr = 0; rr < 4; rr++) {
                float inv = rsqrtf(ss[rr] * (1.0f / D) + EPS);
                float tv = inv * myt[rr];
                gv[rr] = 0.5f * tv *
                    (1.0f + tanhf(0.7978845608028654f * (tv + 0.044715f * tv * tv * tv)));
            }
            gw[lane * 2]     = pk(gv[0], gv[1]);
            gw[lane * 2 + 1] = pk(gv[2], gv[3]);
        }
        __syncwarp();

        // ---------------- pass 2 ----------------
#pragma unroll 1
        for (int it = 0; it < 16; it++) {
            int d0 = it * 128 + lane * 4;
            float4 na, nb, nc, nd;
            if (it != 15) {
                int dn = d0 + 128;
                na = *(const float4*)(xp + dn);
                nb = *(const float4*)(xp + D + dn);
                nc = *(const float4*)(xp + 2 * D + dn);
                nd = *(const float4*)(xp + 3 * D + dn);
            }
            float A[4], Bv[4], C[4], Dv[4];
            *(float4*)A = xa; *(float4*)Bv = xb; *(float4*)C = xc; *(float4*)Dv = xd;

            float vv[RS][4];
#pragma unroll
            for (int r = 0; r < RS; r++)
                *(float4*)vv[r] = *(const float4*)(Vs + r * D + d0);

            ull o0[4], o1[4];
#pragma unroll
            for (int d = 0; d < 4; d++) {
                ull p0 = pk(A[d], Bv[d]);
                ull p1 = pk(C[d], Dv[d]);
#pragma unroll
                for (int r = 0; r < RS; r++) {
                    ull v2 = pk1(vv[r][d]);
                    p0 = f2fma(h0[r], v2, p0);
                    p1 = f2fma(h1[r], v2, p1);
                }
                o0[d] = p0; o1[d] = p1;
            }
#pragma unroll
            for (int j = 0; j < RF; j++) {
                ulonglong2 gj = *(const ulonglong2*)(gw + j * 2);  // broadcast LDS.128
                float wv[4];
                *(float4*)wv = __ldg((const float4*)(W2 + j * D + d0)); // L2-resident
#pragma unroll
                for (int d = 0; d < 4; d++) {
                    ull w2p = pk1(wv[d]);
                    o0[d] = f2fma(gj.x, w2p, o0[d]);
                    o1[d] = f2fma(gj.y, w2p, o1[d]);
                }
            }
            float oa[4], ob[4], oc[4], od[4];
#pragma unroll
            for (int d = 0; d < 4; d++) {
                upk(o0[d], oa[d], ob[d]);
                upk(o1[d], oc[d], od[d]);
            }
            __stcs((float4*)(op + d0),         *(float4*)oa);
            __stcs((float4*)(op + D + d0),     *(float4*)ob);
            __stcs((float4*)(op + 2 * D + d0), *(float4*)oc);
            __stcs((float4*)(op + 3 * D + d0), *(float4*)od);

            xa = na; xb = nb; xc = nc; xd = nd;
        }
    }
}

// ============================================================================
extern "C" void kernel_launch(void* const* d_in, const int* in_sizes, int n_in,
                              void* d_out, int out_size) {
    const float* x   = (const float*)d_in[0];
    const float* n1w = (const float*)d_in[1];
    const float* U   = (const float*)d_in[2];
    const float* lam = (const float*)d_in[3];
    const float* V   = (const float*)d_in[4];
    const float* n2w = (const float*)d_in[5];
    const float* W1  = (const float*)d_in[6];
    const float* W2  = (const float*)d_in[7];
    float* out = (float*)d_out;

    const int smem1 = RS * D * (int)sizeof(float);           // 48 KB
    const int smem3 = (RS + RF) * D * (int)sizeof(float)
                      + (T3 / 32) * RF * 2 * (int)sizeof(ull); // 216K + 3.4K

    cudaFuncSetAttribute(k1_kernel,
                         cudaFuncAttributeMaxDynamicSharedMemorySize, smem1);
    cudaFuncSetAttribute(k3_fused,
                         cudaFuncAttributeMaxDynamicSharedMemorySize, smem3);

    k1_kernel<<<592, 256, smem1>>>(x, n1w, U);          // 4 CTAs/SM
    k2_scan<<<BB * RS, 128>>>(lam);
    k3_fused<<<148, T3, smem3>>>(x, V, n2w, W1, W2, out);
}